// round 9
// baseline (speedup 1.0000x reference)
#include <cuda_runtime.h>
#include <cstdint>
#include <cstddef>

#define Bb 8
#define Ss 4096
#define Dd 64
#define ROWS 32
#define KT 64

__device__ float g_rowsum[Bb * Ss];
__device__ int   g_mask_kind;   // 0 = int32, 1 = bytes(bool), 2 = float32

// Classify the mask buffer dtype by scanning its first 64K 32-bit words.
__global__ void detect_mask(const unsigned* __restrict__ M) {
    __shared__ int s_bytes, s_float;
    if (threadIdx.x == 0) { s_bytes = 0; s_float = 0; }
    __syncthreads();
    int anyBig = 0, anyFloat = 0;
    for (int i = threadIdx.x; i < 65536; i += 256) {
        unsigned w = M[i];
        anyBig   |= (w > 1u);
        anyFloat |= (w == 0x3F800000u);
    }
    if (anyBig)   atomicOr(&s_bytes, 1);
    if (anyFloat) atomicOr(&s_float, 1);
    __syncthreads();
    if (threadIdx.x == 0)
        g_mask_kind = s_float ? 2 : (s_bytes ? 1 : 0);
}

// Packed 2-wide fp32 FMA (SASS FFMA2) — only reachable via PTX fma.rn.f32x2.
__device__ __forceinline__ float2 ffma2(float2 a, float2 b, float2 c) {
    float2 d;
    asm("fma.rn.f32x2 %0, %1, %2, %3;"
        : "=l"(reinterpret_cast<unsigned long long&>(d))
        : "l"(reinterpret_cast<unsigned long long&>(a)),
          "l"(reinterpret_cast<unsigned long long&>(b)),
          "l"(reinterpret_cast<unsigned long long&>(c)));
    return d;
}

__device__ __forceinline__ float2 dup2(float f) {
    float2 d;
    asm("mov.b64 %0, {%1, %1};"
        : "=l"(reinterpret_cast<unsigned long long&>(d)) : "f"(f));
    return d;
}

// Fast exp via all-FFMA path (avoid MUFU EX2 throughput wall: rt=8/SMSP).
__device__ __forceinline__ float fexp(float x) {
    x = fminf(fmaxf(x, -80.0f), 80.0f);
    float t = x * 1.4426950408889634f;
    float r = t + 12582912.0f;              // 1.5*2^23: round-to-nearest in mantissa
    int   ni = __float_as_int(r) - 0x4B400000;
    float n = r - 12582912.0f;
    float f = t - n;                        // f in [-0.5, 0.5]
    float w = f * 0.6931471805599453f;      // |w| <= 0.3466
    float p = fmaf(w, 0.008333333333f, 0.041666666667f);
    p = fmaf(w, p, 0.166666666667f);
    p = fmaf(w, p, 0.5f);
    p = fmaf(w, p, 1.0f);
    p = fmaf(w, p, 1.0f);
    return __int_as_float(__float_as_int(p) + (ni << 23));
}

template<int KIND>
__device__ __forceinline__ bool mask_at(const void* __restrict__ M, size_t off) {
    if (KIND == 0) return ((const int*)M)[off] != 0;
    if (KIND == 1) return ((const uint8_t*)M)[off] != 0;
    return ((const float*)M)[off] != 0.0f;
}

template<int KIND>
__global__ __launch_bounds__(256, 2)
void attn_k1(const float* __restrict__ Qg, const float* __restrict__ Kg,
             const float* __restrict__ Vg, const void* __restrict__ Mg,
             float* __restrict__ ctxg, float* __restrict__ attng) {
    if (g_mask_kind != KIND) return;   // uniform early exit for wrong-dtype variant

    // Static smem: 8192 (Q) + 16384 (K) + 16384 (V) + 8192 (E) = 48 KB
    __shared__ float4 Qs[ROWS * 16];      // [row][d4]
    __shared__ float4 Ks[16 * 64];        // [d4][k]
    __shared__ float4 Vs[64 * 16];        // [k][d4]
    __shared__ float  Es[64 * 32];        // [k][row ^ (k&31)]  (XOR swizzle)

    const int t  = threadIdx.x;
    const int cg = t & 15;                // column group: cols = cg + 16j
    const int rp = t >> 4;                // 0..15: rows rp and rp+16
    const int b  = blockIdx.x >> 7;       // 128 q-tiles per batch
    const int q0 = (blockIdx.x & 127) * ROWS;
    const size_t row0g = (size_t)b * Ss + q0;

    {
        const float4* Qgm = (const float4*)(Qg + row0g * Dd);
        Qs[t]       = Qgm[t];
        Qs[t + 256] = Qgm[t + 256];
    }

    // Packed context accumulators: rows A/B x component pairs (x,y),(z,w)
    float2 accA01 = make_float2(0.f, 0.f), accA23 = make_float2(0.f, 0.f);
    float2 accB01 = make_float2(0.f, 0.f), accB23 = make_float2(0.f, 0.f);
    float rs0 = 0.f, rs1 = 0.f;

    const size_t rowA = row0g + rp;
    const size_t rowB = row0g + rp + 16;

    __syncthreads();

    for (int kt = 0; kt < Ss / KT; kt++) {
        const int k0 = kt * KT;
        {
            const float4* Kgm = (const float4*)(Kg + ((size_t)b * Ss + k0) * Dd);
            const float4* Vgm = (const float4*)(Vg + ((size_t)b * Ss + k0) * Dd);
            #pragma unroll
            for (int m = 0; m < 4; m++) {
                int idx = t + 256 * m;
                int k = idx >> 4, d4 = idx & 15;
                Ks[d4 * 64 + k] = Kgm[idx];
                Vs[idx]         = Vgm[idx];
            }
        }
        __syncthreads();

        // --- QK^T packed: lo half accumulates even-d, hi half odd-d ---
        float2 p00 = make_float2(0.f,0.f), p01 = p00, p02 = p00, p03 = p00;
        float2 p10 = p00, p11 = p00, p12 = p00, p13 = p00;
        #pragma unroll
        for (int d4 = 0; d4 < 16; d4++) {
            float4 qa = Qs[rp * 16 + d4];
            float4 qb = Qs[(rp + 16) * 16 + d4];
            float4 k0v = Ks[d4 * 64 + cg];
            float4 k1v = Ks[d4 * 64 + cg + 16];
            float4 k2v = Ks[d4 * 64 + cg + 32];
            float4 k3v = Ks[d4 * 64 + cg + 48];
            float2 qa01 = make_float2(qa.x, qa.y), qa23 = make_float2(qa.z, qa.w);
            float2 qb01 = make_float2(qb.x, qb.y), qb23 = make_float2(qb.z, qb.w);
            p00 = ffma2(qa01, make_float2(k0v.x,k0v.y), p00);
            p00 = ffma2(qa23, make_float2(k0v.z,k0v.w), p00);
            p01 = ffma2(qa01, make_float2(k1v.x,k1v.y), p01);
            p01 = ffma2(qa23, make_float2(k1v.z,k1v.w), p01);
            p02 = ffma2(qa01, make_float2(k2v.x,k2v.y), p02);
            p02 = ffma2(qa23, make_float2(k2v.z,k2v.w), p02);
            p03 = ffma2(qa01, make_float2(k3v.x,k3v.y), p03);
            p03 = ffma2(qa23, make_float2(k3v.z,k3v.w), p03);
            p10 = ffma2(qb01, make_float2(k0v.x,k0v.y), p10);
            p10 = ffma2(qb23, make_float2(k0v.z,k0v.w), p10);
            p11 = ffma2(qb01, make_float2(k1v.x,k1v.y), p11);
            p11 = ffma2(qb23, make_float2(k1v.z,k1v.w), p11);
            p12 = ffma2(qb01, make_float2(k2v.x,k2v.y), p12);
            p12 = ffma2(qb23, make_float2(k2v.z,k2v.w), p12);
            p13 = ffma2(qb01, make_float2(k3v.x,k3v.y), p13);
            p13 = ffma2(qb23, make_float2(k3v.z,k3v.w), p13);
        }

        // --- mask + exp + store unnormalized e ---
        float sv0[4] = {p00.x + p00.y, p01.x + p01.y, p02.x + p02.y, p03.x + p03.y};
        float sv1[4] = {p10.x + p10.y, p11.x + p11.y, p12.x + p12.y, p13.x + p13.y};
        #pragma unroll
        for (int j = 0; j < 4; j++) {
            int kc = cg + 16 * j;
            size_t colg = (size_t)k0 + kc;
            bool mA = mask_at<KIND>(Mg, rowA * Ss + colg);
            bool mB = mask_at<KIND>(Mg, rowB * Ss + colg);
            float eA = mA ? 0.f : fexp(sv0[j] * 0.125f);
            float eB = mB ? 0.f : fexp(sv1[j] * 0.125f);
            attng[rowA * Ss + colg] = eA;
            attng[rowB * Ss + colg] = eB;
            Es[kc * 32 + (rp ^ (kc & 31))]        = eA;
            Es[kc * 32 + ((rp + 16) ^ (kc & 31))] = eB;
            rs0 += eA;
            rs1 += eB;
        }
        __syncthreads();

        // --- context accumulate (packed): acc[r][4cg..4cg+3] += e[r][k]*V[k][:] ---
        #pragma unroll 8
        for (int k = 0; k < KT; k++) {
            float4 vv = Vs[k * 16 + cg];
            float eA = Es[k * 32 + (rp ^ (k & 31))];
            float eB = Es[k * 32 + ((rp + 16) ^ (k & 31))];
            float2 eA2 = dup2(eA);
            float2 eB2 = dup2(eB);
            float2 v01 = make_float2(vv.x, vv.y), v23 = make_float2(vv.z, vv.w);
            accA01 = ffma2(eA2, v01, accA01);
            accA23 = ffma2(eA2, v23, accA23);
            accB01 = ffma2(eB2, v01, accB01);
            accB23 = ffma2(eB2, v23, accB23);
        }
        __syncthreads();
    }

    // Row-sum reduce across the 16 cg lanes (xor offsets <=8 stay in 16-lane half)
    #pragma unroll
    for (int o = 8; o; o >>= 1) {
        rs0 += __shfl_xor_sync(0xffffffffu, rs0, o);
        rs1 += __shfl_xor_sync(0xffffffffu, rs1, o);
    }
    float inv0 = __fdividef(1.0f, rs0);
    float inv1 = __fdividef(1.0f, rs1);

    float4 acc0 = make_float4(accA01.x * inv0, accA01.y * inv0,
                              accA23.x * inv0, accA23.y * inv0);
    float4 acc1 = make_float4(accB01.x * inv1, accB01.y * inv1,
                              accB23.x * inv1, accB23.y * inv1);

    float4* Cg = (float4*)ctxg;
    Cg[rowA * 16 + cg] = acc0;
    Cg[rowB * 16 + cg] = acc1;

    if (cg == 0) {
        g_rowsum[rowA] = rs0;
        g_rowsum[rowB] = rs1;
    }
}

// Normalize attn rows by 1/rowsum. 32768 blocks x 256 thr, 4 float4 each.
__global__ __launch_bounds__(256)
void attn_k2(float* __restrict__ attng) {
    const int row = blockIdx.x;
    const float inv = __fdividef(1.0f, g_rowsum[row]);
    float4* a = (float4*)(attng + (size_t)row * Ss);
    #pragma unroll
    for (int i = 0; i < 4; i++) {
        int idx = threadIdx.x + 256 * i;
        float4 v = a[idx];
        v.x *= inv; v.y *= inv; v.z *= inv; v.w *= inv;
        a[idx] = v;
    }
}

extern "C" void kernel_launch(void* const* d_in, const int* in_sizes, int n_in,
                              void* d_out, int out_size) {
    const float* Q = (const float*)d_in[0];
    const float* K = (const float*)d_in[1];
    const float* V = (const float*)d_in[2];
    const void*  M = d_in[3];

    float* ctx  = (float*)d_out;                       // [B,S,D]
    float* attn = ctx + (size_t)Bb * Ss * Dd;          // [B,S,S]

    detect_mask<<<1, 256>>>((const unsigned*)M);
    attn_k1<0><<<Bb * (Ss / ROWS), 256>>>(Q, K, V, M, ctx, attn);
    attn_k1<1><<<Bb * (Ss / ROWS), 256>>>(Q, K, V, M, ctx, attn);
    attn_k1<2><<<Bb * (Ss / ROWS), 256>>>(Q, K, V, M, ctx, attn);
    attn_k2<<<Bb * Ss, 256>>>(attn);
}

// round 10
// speedup vs baseline: 2.4208x; 2.4208x over previous
#include <cuda_runtime.h>
#include <cuda_bf16.h>
#include <cstdint>
#include <cstddef>

#define Bb 8
#define Ss 4096
#define Dd 64
#define QT 64           // q rows per CTA
#define KT 64           // k cols per tile
#define LDP 72          // padded smem row length (bf16 elems): banks = lane, conflict-free

__device__ float    g_rowsum[Bb * Ss];
__device__ int      g_mask_kind;            // 0=int32, 1=bytes, 2=float32
__device__ uint16_t g_Qhi[Bb*Ss*Dd], g_Qlo[Bb*Ss*Dd];
__device__ uint16_t g_Khi[Bb*Ss*Dd], g_Klo[Bb*Ss*Dd];
__device__ uint16_t g_Vthi[Bb*Ss*Dd], g_Vtlo[Bb*Ss*Dd];   // transposed: [b][d][s]

// ---------- small helpers ----------
__device__ __forceinline__ float hipart(float a) {          // truncate to bf16 grid
    return __uint_as_float(__float_as_uint(a) & 0xFFFF0000u);
}
__device__ __forceinline__ uint32_t hi2(float a, float b) { // {bf16(b),bf16(a)} truncated
    return __byte_perm(__float_as_uint(a), __float_as_uint(b), 0x7632);
}
__device__ __forceinline__ uint32_t lo2(float a, float b) { // bf16x2 of residuals
    float la = a - hipart(a), lb = b - hipart(b);
    uint32_t r;
    asm("cvt.rn.bf16x2.f32 %0, %1, %2;" : "=r"(r) : "f"(lb), "f"(la));
    return r;
}
__device__ __forceinline__ uint16_t bf16rn(float x) {
    uint32_t r;
    asm("cvt.rn.bf16x2.f32 %0, %1, %1;" : "=r"(r) : "f"(x));
    return (uint16_t)(r & 0xFFFFu);
}
// m16n8k16 row.col bf16 MMA, f32 accumulate
__device__ __forceinline__ void mma_bf16(float* c, uint32_t a0, uint32_t a1,
                                         uint32_t a2, uint32_t a3,
                                         uint32_t b0, uint32_t b1) {
    asm volatile(
        "mma.sync.aligned.m16n8k16.row.col.f32.bf16.bf16.f32 "
        "{%0,%1,%2,%3},{%4,%5,%6,%7},{%8,%9},{%0,%1,%2,%3};"
        : "+f"(c[0]), "+f"(c[1]), "+f"(c[2]), "+f"(c[3])
        : "r"(a0), "r"(a1), "r"(a2), "r"(a3), "r"(b0), "r"(b1));
}
// Fast exp: all-FFMA path (no MUFU)
__device__ __forceinline__ float fexp(float x) {
    x = fminf(fmaxf(x, -80.0f), 80.0f);
    float t = x * 1.4426950408889634f;
    float r = t + 12582912.0f;
    int   ni = __float_as_int(r) - 0x4B400000;
    float n = r - 12582912.0f;
    float f = t - n;
    float w = f * 0.6931471805599453f;
    float p = fmaf(w, 0.008333333333f, 0.041666666667f);
    p = fmaf(w, p, 0.166666666667f);
    p = fmaf(w, p, 0.5f);
    p = fmaf(w, p, 1.0f);
    p = fmaf(w, p, 1.0f);
    return __int_as_float(__float_as_int(p) + (ni << 23));
}

// ---------- mask dtype handling ----------
__global__ void detect_mask(const unsigned* __restrict__ M) {
    __shared__ int s_bytes, s_float;
    if (threadIdx.x == 0) { s_bytes = 0; s_float = 0; }
    __syncthreads();
    int anyBig = 0, anyFloat = 0;
    for (int i = threadIdx.x; i < 65536; i += 256) {
        unsigned w = M[i];
        anyBig   |= (w > 1u);
        anyFloat |= (w == 0x3F800000u);
    }
    if (anyBig)   atomicOr(&s_bytes, 1);
    if (anyFloat) atomicOr(&s_float, 1);
    __syncthreads();
    if (threadIdx.x == 0)
        g_mask_kind = s_float ? 2 : (s_bytes ? 1 : 0);
}
template<int KIND>
__device__ __forceinline__ void mask2(const void* __restrict__ M, size_t off,
                                      bool& m0, bool& m1) {
    if (KIND == 0) { int2 v = *(const int2*)((const int*)M + off); m0 = v.x != 0; m1 = v.y != 0; }
    else if (KIND == 1) { const uint8_t* p = (const uint8_t*)M + off; m0 = p[0] != 0; m1 = p[1] != 0; }
    else { float2 v = *(const float2*)((const float*)M + off); m0 = v.x != 0.f; m1 = v.y != 0.f; }
}

// ---------- prologue: split Q/K into hi/lo bf16 ----------
__global__ __launch_bounds__(256)
void conv_split(const float4* __restrict__ Q, const float4* __restrict__ K) {
    int i = blockIdx.x * 256 + threadIdx.x;        // 524288 float4 per tensor
    float4 q = Q[i], k = K[i];
    ((uint2*)g_Qhi)[i] = make_uint2(hi2(q.x, q.y), hi2(q.z, q.w));
    ((uint2*)g_Qlo)[i] = make_uint2(lo2(q.x, q.y), lo2(q.z, q.w));
    ((uint2*)g_Khi)[i] = make_uint2(hi2(k.x, k.y), hi2(k.z, k.w));
    ((uint2*)g_Klo)[i] = make_uint2(lo2(k.x, k.y), lo2(k.z, k.w));
}

// ---------- prologue: transpose V -> Vt[b][d][s], split hi/lo ----------
__global__ __launch_bounds__(256)
void conv_vt(const float* __restrict__ V) {
    int b = blockIdx.x >> 6, s0 = (blockIdx.x & 63) * 64;
    __shared__ float sV[64 * 65];
    int t = threadIdx.x;
    #pragma unroll
    for (int m = 0; m < 16; m++) {
        int j = t + 256 * m; int s = j >> 6, d = j & 63;
        sV[s * 65 + d] = V[((size_t)(b * Ss) + s0 + s) * Dd + d];
    }
    __syncthreads();
    #pragma unroll
    for (int m = 0; m < 16; m++) {
        int j = t + 256 * m; int d = j >> 6, s = j & 63;
        float x = sV[s * 65 + d];
        size_t off = ((size_t)(b * Dd) + d) * Ss + s0 + s;
        g_Vthi[off] = (uint16_t)(__float_as_uint(x) >> 16);
        g_Vtlo[off] = bf16rn(x - hipart(x));
    }
}

// ---------- tile loader: 64 rows x 64 bf16 -> padded smem ----------
__device__ __forceinline__ void ldtile(const uint16_t* __restrict__ g, int gstride8,
                                       uint16_t* __restrict__ s, int t) {
    const uint4* gp = (const uint4*)g;
    #pragma unroll
    for (int m = 0; m < 2; m++) {
        int idx = t + 256 * m;
        int r = idx >> 3, sg = idx & 7;
        *(uint4*)(s + r * LDP + sg * 8) = gp[r * gstride8 + sg];
    }
}

// ---------- main attention kernel ----------
template<int KIND>
__global__ __launch_bounds__(256, 2)
void attn_k1(const void* __restrict__ Mg, float* __restrict__ ctxg,
             float* __restrict__ attng) {
    if (g_mask_kind != KIND) return;

    __shared__ __align__(16) uint16_t sKhi[QT * LDP];
    __shared__ __align__(16) uint16_t sKlo[QT * LDP];
    __shared__ __align__(16) uint16_t sVhi[QT * LDP];
    __shared__ __align__(16) uint16_t sVlo[QT * LDP];

    const int t   = threadIdx.x;
    const int l   = t & 31;
    const int wid = t >> 5;
    const int wm  = wid & 3;          // row group: rows wm*16 + ...
    const int wn  = wid >> 2;         // k-col half (0/1)
    const int lr  = l >> 2;           // 0..7
    const int lc2 = 2 * (l & 3);      // 0,2,4,6
    const int b   = blockIdx.x >> 6;
    const int q0  = (blockIdx.x & 63) * QT;

    // --- stage Q tile, extract A fragments into registers (hi/lo) ---
    ldtile(g_Qhi + ((size_t)(b * Ss) + q0) * Dd, 8, sKhi, t);
    ldtile(g_Qlo + ((size_t)(b * Ss) + q0) * Dd, 8, sKlo, t);
    __syncthreads();
    uint32_t aQh[4][4], aQl[4][4];
    #pragma unroll
    for (int ks = 0; ks < 4; ks++) {
        int o = (wm * 16 + lr) * LDP + ks * 16 + lc2;
        aQh[ks][0] = *(const uint32_t*)(sKhi + o);
        aQh[ks][1] = *(const uint32_t*)(sKhi + o + 8 * LDP);
        aQh[ks][2] = *(const uint32_t*)(sKhi + o + 8);
        aQh[ks][3] = *(const uint32_t*)(sKhi + o + 8 * LDP + 8);
        aQl[ks][0] = *(const uint32_t*)(sKlo + o);
        aQl[ks][1] = *(const uint32_t*)(sKlo + o + 8 * LDP);
        aQl[ks][2] = *(const uint32_t*)(sKlo + o + 8);
        aQl[ks][3] = *(const uint32_t*)(sKlo + o + 8 * LDP + 8);
    }
    __syncthreads();

    float d2[8][4];
    #pragma unroll
    for (int nd = 0; nd < 8; nd++)
        d2[nd][0] = d2[nd][1] = d2[nd][2] = d2[nd][3] = 0.f;
    float rs0 = 0.f, rs1 = 0.f;

    const size_t rowAg = (size_t)b * Ss + q0 + wm * 16 + lr;
    const size_t rowBg = rowAg + 8;

    for (int kt = 0; kt < Ss / KT; kt++) {
        const int k0 = kt * KT;
        ldtile(g_Khi  + ((size_t)(b * Ss) + k0) * Dd, 8,   sKhi, t);
        ldtile(g_Klo  + ((size_t)(b * Ss) + k0) * Dd, 8,   sKlo, t);
        ldtile(g_Vthi + (size_t)(b * Dd) * Ss + k0, 512,   sVhi, t);
        ldtile(g_Vtlo + (size_t)(b * Dd) * Ss + k0, 512,   sVlo, t);
        __syncthreads();

        // --- QK^T: 16 rows x 32 cols per warp, 3-term bf16 emulation ---
        float c[4][4];
        #pragma unroll
        for (int nt = 0; nt < 4; nt++)
            c[nt][0] = c[nt][1] = c[nt][2] = c[nt][3] = 0.f;
        #pragma unroll
        for (int ks = 0; ks < 4; ks++) {
            #pragma unroll
            for (int nt = 0; nt < 4; nt++) {
                int o = (wn * 32 + nt * 8 + lr) * LDP + ks * 16 + lc2;
                uint32_t bh0 = *(const uint32_t*)(sKhi + o);
                uint32_t bh1 = *(const uint32_t*)(sKhi + o + 8);
                uint32_t bl0 = *(const uint32_t*)(sKlo + o);
                uint32_t bl1 = *(const uint32_t*)(sKlo + o + 8);
                mma_bf16(c[nt], aQh[ks][0], aQh[ks][1], aQh[ks][2], aQh[ks][3], bh0, bh1);
                mma_bf16(c[nt], aQh[ks][0], aQh[ks][1], aQh[ks][2], aQh[ks][3], bl0, bl1);
                mma_bf16(c[nt], aQl[ks][0], aQl[ks][1], aQl[ks][2], aQl[ks][3], bh0, bh1);
            }
        }

        // --- epilogue: mask + exp + attn store + e hi/lo pack (P->A reuse) ---
        uint32_t eAh[4], eAl[4], eBh[4], eBl[4];
        #pragma unroll
        for (int nt = 0; nt < 4; nt++) {
            int colg = k0 + wn * 32 + nt * 8 + lc2;
            bool m0, m1, m2, m3;
            mask2<KIND>(Mg, rowAg * Ss + colg, m0, m1);
            mask2<KIND>(Mg, rowBg * Ss + colg, m2, m3);
            float e0 = m0 ? 0.f : fexp(0.125f * c[nt][0]);
            float e1 = m1 ? 0.f : fexp(0.125f * c[nt][1]);
            float e2 = m2 ? 0.f : fexp(0.125f * c[nt][2]);
            float e3 = m3 ? 0.f : fexp(0.125f * c[nt][3]);
            *(float2*)(attng + rowAg * Ss + colg) = make_float2(e0, e1);
            *(float2*)(attng + rowBg * Ss + colg) = make_float2(e2, e3);
            rs0 += e0 + e1;
            rs1 += e2 + e3;
            eAh[nt] = hi2(e0, e1); eAl[nt] = lo2(e0, e1);
            eBh[nt] = hi2(e2, e3); eBl[nt] = lo2(e2, e3);
        }

        // --- AV: d2[16 rows x 64 d] += e (this warp's 32 kc) * Vt ---
        #pragma unroll
        for (int kv = 0; kv < 2; kv++) {
            uint32_t Ah0 = eAh[2*kv], Ah1 = eBh[2*kv], Ah2 = eAh[2*kv+1], Ah3 = eBh[2*kv+1];
            uint32_t Al0 = eAl[2*kv], Al1 = eBl[2*kv], Al2 = eAl[2*kv+1], Al3 = eBl[2*kv+1];
            #pragma unroll
            for (int nd = 0; nd < 8; nd++) {
                int o = (nd * 8 + lr) * LDP + wn * 32 + kv * 16 + lc2;
                uint32_t bh0 = *(const uint32_t*)(sVhi + o);
                uint32_t bh1 = *(const uint32_t*)(sVhi + o + 8);
                uint32_t bl0 = *(const uint32_t*)(sVlo + o);
                uint32_t bl1 = *(const uint32_t*)(sVlo + o + 8);
                mma_bf16(d2[nd], Ah0, Ah1, Ah2, Ah3, bh0, bh1);
                mma_bf16(d2[nd], Ah0, Ah1, Ah2, Ah3, bl0, bl1);
                mma_bf16(d2[nd], Al0, Al1, Al2, Al3, bh0, bh1);
            }
        }
        __syncthreads();
    }

    // --- rowsum: reduce over the 4 lanes sharing a row ---
    rs0 += __shfl_xor_sync(0xffffffffu, rs0, 1);
    rs0 += __shfl_xor_sync(0xffffffffu, rs0, 2);
    rs1 += __shfl_xor_sync(0xffffffffu, rs1, 1);
    rs1 += __shfl_xor_sync(0xffffffffu, rs1, 2);

    // --- combine the two kc-half warps via smem, normalize, store ---
    float* redD = (float*)sKhi;                 // 4096 floats (16 KB) fits in 18 KB
    float* redR = (float*)sVhi;                 // 64 floats
    const int r0 = wm * 16 + lr;
    if (wn == 1) {
        #pragma unroll
        for (int nd = 0; nd < 8; nd++) {
            int c0 = nd * 8 + lc2;
            redD[r0 * 64 + c0]           = d2[nd][0];
            redD[r0 * 64 + c0 + 1]       = d2[nd][1];
            redD[(r0 + 8) * 64 + c0]     = d2[nd][2];
            redD[(r0 + 8) * 64 + c0 + 1] = d2[nd][3];
        }
        if ((l & 3) == 0) { redR[r0] = rs0; redR[r0 + 8] = rs1; }
    }
    __syncthreads();
    if (wn == 0) {
        float rsT0 = rs0 + redR[r0];
        float rsT1 = rs1 + redR[r0 + 8];
        float inv0 = __fdividef(1.0f, rsT0);
        float inv1 = __fdividef(1.0f, rsT1);
        #pragma unroll
        for (int nd = 0; nd < 8; nd++) {
            int c0 = nd * 8 + lc2;
            float o0 = (d2[nd][0] + redD[r0 * 64 + c0])           * inv0;
            float o1 = (d2[nd][1] + redD[r0 * 64 + c0 + 1])       * inv0;
            float o2 = (d2[nd][2] + redD[(r0 + 8) * 64 + c0])     * inv1;
            float o3 = (d2[nd][3] + redD[(r0 + 8) * 64 + c0 + 1]) * inv1;
            *(float2*)(ctxg + rowAg * Dd + c0) = make_float2(o0, o1);
            *(float2*)(ctxg + rowBg * Dd + c0) = make_float2(o2, o3);
        }
        if ((l & 3) == 0) {
            g_rowsum[rowAg] = rsT0;
            g_rowsum[rowBg] = rsT1;
        }
    }
}

// ---------- attn row normalization ----------
__global__ __launch_bounds__(256)
void attn_k2(float* __restrict__ attng) {
    const int row = blockIdx.x;
    const float inv = __fdividef(1.0f, g_rowsum[row]);
    float4* a = (float4*)(attng + (size_t)row * Ss);
    #pragma unroll
    for (int i = 0; i < 4; i++) {
        int idx = threadIdx.x + 256 * i;
        float4 v = a[idx];
        v.x *= inv; v.y *= inv; v.z *= inv; v.w *= inv;
        a[idx] = v;
    }
}

extern "C" void kernel_launch(void* const* d_in, const int* in_sizes, int n_in,
                              void* d_out, int out_size) {
    const float* Q = (const float*)d_in[0];
    const float* K = (const float*)d_in[1];
    const float* V = (const float*)d_in[2];
    const void*  M = d_in[3];

    float* ctx  = (float*)d_out;                      // [B,S,D]
    float* attn = ctx + (size_t)Bb * Ss * Dd;         // [B,S,S]

    conv_split<<<2048, 256>>>((const float4*)Q, (const float4*)K);
    conv_vt<<<Bb * (Ss / 64), 256>>>(V);
    detect_mask<<<1, 256>>>((const unsigned*)M);
    attn_k1<0><<<Bb * (Ss / QT), 256>>>(M, ctx, attn);
    attn_k1<1><<<Bb * (Ss / QT), 256>>>(M, ctx, attn);
    attn_k1<2><<<Bb * (Ss / QT), 256>>>(M, ctx, attn);
    attn_k2<<<Bb * Ss, 256>>>(attn);
}